// round 11
// baseline (speedup 1.0000x reference)
#include <cuda_runtime.h>
#include <cuda_bf16.h>
#include <cuda_fp16.h>
#include <cstdint>

// ROIAlign, OUT=15x15, SCALE=1/16, SR=2
// x: [2,256,64,64] f32; boxes: [512,4] f32; batch_idx: [512] i32
// out: [512,256,15,15] f32
//
// v6: v5 (separable, 32-ch chunks) with FP16 vrow intermediate:
//   stage1 (fp32 acc) -> round to half -> vrow (11.5KB smem)
//   stage2: LDS.128 = 8 channels (vs 4 for fp32) -> ~2x fewer smem wavefronts.

#define HH 64
#define WW 64
#define CC 256
#define OUT_HW 15
#define NBOX 512
#define PW 12
#define NCHUNK 8                         // 32 channels per chunk
#define NPOS (OUT_HW * PW)               // 180
#define VQ 4                             // uint4 (8 half) per position = 32 ch

#define SMEM_DYN (NPOS * VQ * 16)        // 11520 B

// vrow index, 16B-granular XOR swizzle
#define VIDX(pos, q) (((pos) * VQ) + ((q) ^ ((pos) & 3)))

// channels-last scratch: [2,64,64,256] f32 = 8MB
__device__ float g_xt[2 * HH * WW * CC];

// ---------------------------------------------------------------------------
// Transpose [B,C,H*W] -> [B,H*W,C] via 32x32 smem tiles
// ---------------------------------------------------------------------------
__global__ __launch_bounds__(256) void transpose_kernel(const float* __restrict__ x) {
    __shared__ float tile[32][33];
    int b   = blockIdx.z;
    int hw0 = blockIdx.x * 32;
    int c0  = blockIdx.y * 32;
    const float* src = x + ((size_t)b * CC) * (HH * WW);
    #pragma unroll
    for (int i = threadIdx.y; i < 32; i += 8)
        tile[i][threadIdx.x] = src[(size_t)(c0 + i) * (HH * WW) + hw0 + threadIdx.x];
    __syncthreads();
    float* dst = g_xt + (size_t)b * (HH * WW) * CC;
    #pragma unroll
    for (int i = threadIdx.y; i < 32; i += 8)
        dst[(size_t)(hw0 + i) * CC + c0 + threadIdx.x] = tile[threadIdx.x][i];
}

// ---------------------------------------------------------------------------
// Axis corner-list builder (dedup 2 subsamples -> <=3 corners). v = valid*0.5.
// ---------------------------------------------------------------------------
__device__ __forceinline__ void axis_bin(float a1, float bin, int bin_i,
                                         int size, int* o_idx, float* o_wt, int* o_n) {
    int   idx[3];
    float wt[3];
    int   cnt = 0;
    #pragma unroll
    for (int s = 0; s < 2; s++) {
        float p = a1 + ((float)(bin_i * 2 + s) + 0.5f) * 0.5f * bin;
        const float v = (p >= -1.0f && p <= (float)size) ? 0.5f : 0.0f;
        p = fminf(fmaxf(p, 0.0f), (float)(size - 1));
        int lo = (int)floorf(p);
        if (lo > size - 1) lo = size - 1;
        const int   hi = min(lo + 1, size - 1);
        const float f  = p - (float)lo;
        int   ci[2] = { lo, hi };
        float cw[2] = { (1.0f - f) * v, f * v };
        #pragma unroll
        for (int k = 0; k < 2; k++) {
            int m;
            for (m = 0; m < cnt; m++)
                if (idx[m] == ci[k]) { wt[m] += cw[k]; break; }
            if (m == cnt && cnt < 3) { idx[cnt] = ci[k]; wt[cnt] = cw[k]; cnt++; }
        }
    }
    *o_n = cnt;
    for (int m = 0; m < cnt; m++) { o_idx[m] = idx[m]; o_wt[m] = wt[m]; }
}

// ---------------------------------------------------------------------------
// ROI kernel: grid (8 chunk, 512 box), 256 threads.
// ---------------------------------------------------------------------------
__global__ __launch_bounds__(256) void roi_kernel(const float* __restrict__ boxes,
                                                  const int* __restrict__ batch_idx,
                                                  float* __restrict__ out) {
    extern __shared__ uint4 vrow[];      // swizzled [pos 0..179][q 0..3], 8 half each

    __shared__ int    s_xn[OUT_HW];
    __shared__ int    s_xc[OUT_HW][3];   // relative x (0..11)
    __shared__ float  s_xw[OUT_HW][3];
    __shared__ int    s_yn[OUT_HW];
    __shared__ int    s_yoff[OUT_HW][3]; // absolute row offset into g_xt (floats)
    __shared__ float  s_yw[OUT_HW][3];

    const int chunk = blockIdx.x;
    const int n     = blockIdx.y;
    const int tid   = threadIdx.x;

    // ---- box geometry (broadcast loads) ----
    const float bx1 = boxes[n * 4 + 0] * 0.0625f;
    const float by1 = boxes[n * 4 + 1] * 0.0625f;
    const float bx2 = boxes[n * 4 + 2] * 0.0625f;
    const float by2 = boxes[n * 4 + 3] * 0.0625f;
    const float bin_w = fmaxf(bx2 - bx1, 1.0f) * (1.0f / OUT_HW);
    const float bin_h = fmaxf(by2 - by1, 1.0f) * (1.0f / OUT_HW);
    const int   b     = batch_idx[n];

    float p0x = fminf(fmaxf(bx1 + 0.25f * bin_w, 0.0f), (float)(WW - 1));
    const int x_base = (int)floorf(p0x);

    // ---- per-bin axis corner lists ----
    if (tid < OUT_HW) {
        int idx[3]; float wt[3]; int cnt;
        axis_bin(bx1, bin_w, tid, WW, idx, wt, &cnt);
        s_xn[tid] = cnt;
        for (int m = 0; m < cnt; m++) { s_xc[tid][m] = idx[m] - x_base; s_xw[tid][m] = wt[m]; }
    } else if (tid >= 32 && tid < 32 + OUT_HW) {
        const int h = tid - 32;
        int idx[3]; float wt[3]; int cnt;
        axis_bin(by1, bin_h, h, HH, idx, wt, &cnt);
        s_yn[h] = cnt;
        for (int m = 0; m < cnt; m++) {
            s_yoff[h][m] = (b * (HH * WW) + idx[m] * WW) * CC;
            s_yw[h][m]   = wt[m];
        }
    }
    __syncthreads();

    // ---- stage 1: y-combine (fp32) -> half -> vrow ----
    // item = (pos, q): 8 channels; two contiguous float4 loads per y corner.
    {
        const float* srcc = g_xt + chunk * 32;
        #pragma unroll
        for (int i = tid; i < NPOS * VQ; i += 256) {
            const int q   = i & 3;
            const int pos = i >> 2;          // h*12 + x
            const int h   = pos / PW;
            const int x   = pos - h * PW;
            const int xabs = min(x_base + x, WW - 1);
            const int coff = xabs * CC + q * 8;
            const int ny   = s_yn[h];
            float4 alo = {0.f, 0.f, 0.f, 0.f};
            float4 ahi = {0.f, 0.f, 0.f, 0.f};
            #pragma unroll
            for (int yi = 0; yi < 3; yi++) {
                if (yi < ny) {
                    const float  wy = s_yw[h][yi];
                    const float* p  = srcc + s_yoff[h][yi] + coff;
                    const float4 v0 = *reinterpret_cast<const float4*>(p);
                    const float4 v1 = *reinterpret_cast<const float4*>(p + 4);
                    alo.x = fmaf(wy, v0.x, alo.x); alo.y = fmaf(wy, v0.y, alo.y);
                    alo.z = fmaf(wy, v0.z, alo.z); alo.w = fmaf(wy, v0.w, alo.w);
                    ahi.x = fmaf(wy, v1.x, ahi.x); ahi.y = fmaf(wy, v1.y, ahi.y);
                    ahi.z = fmaf(wy, v1.z, ahi.z); ahi.w = fmaf(wy, v1.w, ahi.w);
                }
            }
            __half2 h0 = __floats2half2_rn(alo.x, alo.y);
            __half2 h1 = __floats2half2_rn(alo.z, alo.w);
            __half2 h2 = __floats2half2_rn(ahi.x, ahi.y);
            __half2 h3 = __floats2half2_rn(ahi.z, ahi.w);
            uint4 u;
            u.x = *reinterpret_cast<uint32_t*>(&h0);
            u.y = *reinterpret_cast<uint32_t*>(&h1);
            u.z = *reinterpret_cast<uint32_t*>(&h2);
            u.w = *reinterpret_cast<uint32_t*>(&h3);
            vrow[VIDX(pos, q)] = u;
        }
    }
    __syncthreads();

    if (tid >= OUT_HW * OUT_HW) return;

    // ---- stage 2: x-combine (fp32 accum), thread = bin ----
    const int h = tid / OUT_HW;
    const int w = tid - h * OUT_HW;

    const int nx = s_xn[w];
    int   pbase[3];
    int   psw[3];
    float wxs[3];
    #pragma unroll
    for (int xi = 0; xi < 3; xi++) {
        const int pos = h * PW + (xi < nx ? s_xc[w][xi] : 0);
        pbase[xi] = pos * VQ;
        psw[xi]   = pos & 3;
        wxs[xi]   = xi < nx ? s_xw[w][xi] : 0.0f;
    }

    // 32 channel accumulators as 16 float2 (channel c = q*8 + 2k (+1))
    float2 acc[16];
    #pragma unroll
    for (int k = 0; k < 16; k++) acc[k] = make_float2(0.f, 0.f);

    #pragma unroll
    for (int xi = 0; xi < 3; xi++) {
        if (xi < nx) {
            const float g  = wxs[xi];
            const int   bb = pbase[xi];
            const int   sw = psw[xi];
            #pragma unroll
            for (int q = 0; q < 4; q++) {
                const uint4 u = vrow[bb + (q ^ sw)];
                const __half2* hp = reinterpret_cast<const __half2*>(&u);
                #pragma unroll
                for (int k = 0; k < 4; k++) {
                    const float2 f = __half22float2(hp[k]);
                    acc[q * 4 + k].x = fmaf(g, f.x, acc[q * 4 + k].x);
                    acc[q * 4 + k].y = fmaf(g, f.y, acc[q * 4 + k].y);
                }
            }
        }
    }

    // out[n, c, h, w]: channel c = chunk*32 + q*8 + 2k(+1); contiguous warp stores.
    float* obase = out + ((size_t)n * CC + chunk * 32) * (OUT_HW * OUT_HW) + tid;
    const int S = OUT_HW * OUT_HW;
    #pragma unroll
    for (int k = 0; k < 16; k++) {
        obase[(2 * k) * S]     = acc[k].x;
        obase[(2 * k + 1) * S] = acc[k].y;
    }
}

// ---------------------------------------------------------------------------
extern "C" void kernel_launch(void* const* d_in, const int* in_sizes, int n_in,
                              void* d_out, int out_size) {
    const float* x     = (const float*)d_in[0];
    const float* boxes = (const float*)d_in[1];
    const int*   bidx  = (const int*)d_in[2];
    float*       out   = (float*)d_out;

    (void)in_sizes; (void)n_in; (void)out_size;

    dim3 tb(32, 8);
    dim3 tg((HH * WW) / 32, CC / 32, 2);
    transpose_kernel<<<tg, tb>>>(x);

    dim3 rg(NCHUNK, NBOX);
    roi_kernel<<<rg, 256, SMEM_DYN>>>(boxes, bidx, out);
}

// round 12
// speedup vs baseline: 1.0174x; 1.0174x over previous
#include <cuda_runtime.h>
#include <cuda_bf16.h>
#include <cuda_fp16.h>
#include <cstdint>

// ROIAlign, OUT=15x15, SCALE=1/16, SR=2
// x: [2,256,64,64] f32; boxes: [512,4] f32; batch_idx: [512] i32
// out: [512,256,15,15] f32
//
// v7: fp16 channels-last scratch (4.2MB, L2-resident) + fp16 vrow.
//   stage1: one uint4 LDG per corner = 8 channels (2x fewer LDG than v6)
//   stage2: LDS.128 = 8 channels, fp32 accumulate, coalesced STG.

#define HH 64
#define WW 64
#define CC 256
#define OUT_HW 15
#define NBOX 512
#define PW 12
#define NCHUNK 8                         // 32 channels per chunk
#define NPOS (OUT_HW * PW)               // 180
#define VQ 4                             // uint4 (8 half) per position = 32 ch

#define SMEM_DYN (NPOS * VQ * 16)        // 11520 B

// vrow index, 16B-granular XOR swizzle
#define VIDX(pos, q) (((pos) * VQ) + ((q) ^ ((pos) & 3)))

// channels-last fp16 scratch: [2,64,64,256] = 4.2MB
__device__ __half g_xt[2 * HH * WW * CC];

// ---------------------------------------------------------------------------
// Transpose [B,C,H*W] f32 -> [B,H*W,C] f16 via 32x32 smem tiles
// ---------------------------------------------------------------------------
__global__ __launch_bounds__(256) void transpose_kernel(const float* __restrict__ x) {
    __shared__ float tile[32][33];
    int b   = blockIdx.z;
    int hw0 = blockIdx.x * 32;
    int c0  = blockIdx.y * 32;
    const float* src = x + ((size_t)b * CC) * (HH * WW);
    #pragma unroll
    for (int i = threadIdx.y; i < 32; i += 8)
        tile[i][threadIdx.x] = src[(size_t)(c0 + i) * (HH * WW) + hw0 + threadIdx.x];
    __syncthreads();
    __half* dst = g_xt + (size_t)b * (HH * WW) * CC;
    #pragma unroll
    for (int i = threadIdx.y; i < 32; i += 8)
        dst[(size_t)(hw0 + i) * CC + c0 + threadIdx.x] = __float2half(tile[threadIdx.x][i]);
}

// ---------------------------------------------------------------------------
// Axis corner-list builder (dedup 2 subsamples -> <=3 corners). v = valid*0.5.
// ---------------------------------------------------------------------------
__device__ __forceinline__ void axis_bin(float a1, float bin, int bin_i,
                                         int size, int* o_idx, float* o_wt, int* o_n) {
    int   idx[3];
    float wt[3];
    int   cnt = 0;
    #pragma unroll
    for (int s = 0; s < 2; s++) {
        float p = a1 + ((float)(bin_i * 2 + s) + 0.5f) * 0.5f * bin;
        const float v = (p >= -1.0f && p <= (float)size) ? 0.5f : 0.0f;
        p = fminf(fmaxf(p, 0.0f), (float)(size - 1));
        int lo = (int)floorf(p);
        if (lo > size - 1) lo = size - 1;
        const int   hi = min(lo + 1, size - 1);
        const float f  = p - (float)lo;
        int   ci[2] = { lo, hi };
        float cw[2] = { (1.0f - f) * v, f * v };
        #pragma unroll
        for (int k = 0; k < 2; k++) {
            int m;
            for (m = 0; m < cnt; m++)
                if (idx[m] == ci[k]) { wt[m] += cw[k]; break; }
            if (m == cnt && cnt < 3) { idx[cnt] = ci[k]; wt[cnt] = cw[k]; cnt++; }
        }
    }
    *o_n = cnt;
    for (int m = 0; m < cnt; m++) { o_idx[m] = idx[m]; o_wt[m] = wt[m]; }
}

// ---------------------------------------------------------------------------
// ROI kernel: grid (8 chunk, 512 box), 256 threads.
// ---------------------------------------------------------------------------
__global__ __launch_bounds__(256) void roi_kernel(const float* __restrict__ boxes,
                                                  const int* __restrict__ batch_idx,
                                                  float* __restrict__ out) {
    extern __shared__ uint4 vrow[];      // swizzled [pos 0..179][q 0..3], 8 half each

    __shared__ int    s_xn[OUT_HW];
    __shared__ int    s_xc[OUT_HW][3];   // relative x (0..11)
    __shared__ float  s_xw[OUT_HW][3];
    __shared__ int    s_yn[OUT_HW];
    __shared__ int    s_yoff[OUT_HW][3]; // absolute row offset into g_xt (halves)
    __shared__ float  s_yw[OUT_HW][3];

    const int chunk = blockIdx.x;
    const int n     = blockIdx.y;
    const int tid   = threadIdx.x;

    // ---- box geometry (broadcast loads) ----
    const float bx1 = boxes[n * 4 + 0] * 0.0625f;
    const float by1 = boxes[n * 4 + 1] * 0.0625f;
    const float bx2 = boxes[n * 4 + 2] * 0.0625f;
    const float by2 = boxes[n * 4 + 3] * 0.0625f;
    const float bin_w = fmaxf(bx2 - bx1, 1.0f) * (1.0f / OUT_HW);
    const float bin_h = fmaxf(by2 - by1, 1.0f) * (1.0f / OUT_HW);
    const int   b     = batch_idx[n];

    float p0x = fminf(fmaxf(bx1 + 0.25f * bin_w, 0.0f), (float)(WW - 1));
    const int x_base = (int)floorf(p0x);

    // ---- per-bin axis corner lists ----
    if (tid < OUT_HW) {
        int idx[3]; float wt[3]; int cnt;
        axis_bin(bx1, bin_w, tid, WW, idx, wt, &cnt);
        s_xn[tid] = cnt;
        for (int m = 0; m < cnt; m++) { s_xc[tid][m] = idx[m] - x_base; s_xw[tid][m] = wt[m]; }
    } else if (tid >= 32 && tid < 32 + OUT_HW) {
        const int h = tid - 32;
        int idx[3]; float wt[3]; int cnt;
        axis_bin(by1, bin_h, h, HH, idx, wt, &cnt);
        s_yn[h] = cnt;
        for (int m = 0; m < cnt; m++) {
            s_yoff[h][m] = (b * (HH * WW) + idx[m] * WW) * CC;
            s_yw[h][m]   = wt[m];
        }
    }
    __syncthreads();

    // ---- stage 1: y-combine (fp32 acc from fp16 src) -> half -> vrow ----
    // item = (pos, q): 8 channels; ONE uint4 load per y corner.
    {
        const __half* srcc = g_xt + chunk * 32;
        #pragma unroll
        for (int i = tid; i < NPOS * VQ; i += 256) {
            const int q   = i & 3;
            const int pos = i >> 2;          // h*12 + x
            const int h   = pos / PW;
            const int x   = pos - h * PW;
            const int xabs = min(x_base + x, WW - 1);
            const int coff = xabs * CC + q * 8;
            const int ny   = s_yn[h];
            float2 a0 = {0.f, 0.f}, a1 = {0.f, 0.f}, a2 = {0.f, 0.f}, a3 = {0.f, 0.f};
            #pragma unroll
            for (int yi = 0; yi < 3; yi++) {
                if (yi < ny) {
                    const float wy = s_yw[h][yi];
                    const uint4 u  = *reinterpret_cast<const uint4*>(srcc + s_yoff[h][yi] + coff);
                    const __half2* hp = reinterpret_cast<const __half2*>(&u);
                    float2 f;
                    f = __half22float2(hp[0]); a0.x = fmaf(wy, f.x, a0.x); a0.y = fmaf(wy, f.y, a0.y);
                    f = __half22float2(hp[1]); a1.x = fmaf(wy, f.x, a1.x); a1.y = fmaf(wy, f.y, a1.y);
                    f = __half22float2(hp[2]); a2.x = fmaf(wy, f.x, a2.x); a2.y = fmaf(wy, f.y, a2.y);
                    f = __half22float2(hp[3]); a3.x = fmaf(wy, f.x, a3.x); a3.y = fmaf(wy, f.y, a3.y);
                }
            }
            __half2 h0 = __floats2half2_rn(a0.x, a0.y);
            __half2 h1 = __floats2half2_rn(a1.x, a1.y);
            __half2 h2 = __floats2half2_rn(a2.x, a2.y);
            __half2 h3 = __floats2half2_rn(a3.x, a3.y);
            uint4 u;
            u.x = *reinterpret_cast<uint32_t*>(&h0);
            u.y = *reinterpret_cast<uint32_t*>(&h1);
            u.z = *reinterpret_cast<uint32_t*>(&h2);
            u.w = *reinterpret_cast<uint32_t*>(&h3);
            vrow[VIDX(pos, q)] = u;
        }
    }
    __syncthreads();

    if (tid >= OUT_HW * OUT_HW) return;

    // ---- stage 2: x-combine (fp32 accum), thread = bin ----
    const int h = tid / OUT_HW;
    const int w = tid - h * OUT_HW;

    const int nx = s_xn[w];
    int   pbase[3];
    int   psw[3];
    float wxs[3];
    #pragma unroll
    for (int xi = 0; xi < 3; xi++) {
        const int pos = h * PW + (xi < nx ? s_xc[w][xi] : 0);
        pbase[xi] = pos * VQ;
        psw[xi]   = pos & 3;
        wxs[xi]   = xi < nx ? s_xw[w][xi] : 0.0f;
    }

    // 32 channel accumulators as 16 float2 (channel c = q*8 + 2k (+1))
    float2 acc[16];
    #pragma unroll
    for (int k = 0; k < 16; k++) acc[k] = make_float2(0.f, 0.f);

    #pragma unroll
    for (int xi = 0; xi < 3; xi++) {
        if (xi < nx) {
            const float g  = wxs[xi];
            const int   bb = pbase[xi];
            const int   sw = psw[xi];
            #pragma unroll
            for (int q = 0; q < 4; q++) {
                const uint4 u = vrow[bb + (q ^ sw)];
                const __half2* hp = reinterpret_cast<const __half2*>(&u);
                #pragma unroll
                for (int k = 0; k < 4; k++) {
                    const float2 f = __half22float2(hp[k]);
                    acc[q * 4 + k].x = fmaf(g, f.x, acc[q * 4 + k].x);
                    acc[q * 4 + k].y = fmaf(g, f.y, acc[q * 4 + k].y);
                }
            }
        }
    }

    // out[n, c, h, w]: channel c = chunk*32 + q*8 + 2k(+1); contiguous warp stores.
    float* obase = out + ((size_t)n * CC + chunk * 32) * (OUT_HW * OUT_HW) + tid;
    const int S = OUT_HW * OUT_HW;
    #pragma unroll
    for (int k = 0; k < 16; k++) {
        obase[(2 * k) * S]     = acc[k].x;
        obase[(2 * k + 1) * S] = acc[k].y;
    }
}

// ---------------------------------------------------------------------------
extern "C" void kernel_launch(void* const* d_in, const int* in_sizes, int n_in,
                              void* d_out, int out_size) {
    const float* x     = (const float*)d_in[0];
    const float* boxes = (const float*)d_in[1];
    const int*   bidx  = (const int*)d_in[2];
    float*       out   = (float*)d_out;

    (void)in_sizes; (void)n_in; (void)out_size;

    dim3 tb(32, 8);
    dim3 tg((HH * WW) / 32, CC / 32, 2);
    transpose_kernel<<<tg, tb>>>(x);

    dim3 rg(NCHUNK, NBOX);
    roi_kernel<<<rg, 256, SMEM_DYN>>>(boxes, bidx, out);
}